// round 1
// baseline (speedup 1.0000x reference)
#include <cuda_runtime.h>
#include <math.h>

#define BATCH 32768

// 128 MB inter-stage scratch: pooled conv2 output, laid out exactly as the
// flattened FC input: g_p2[sample*1024 + oc*16 + pooledpos]
__device__ float g_p2[BATCH * 1024];

// ---------------------------------------------------------------------------
// Kernel A: conv1(1->32,k3,pad1)+ReLU+pool2  ->  conv2(32->64,k3,pad1)+ReLU+pool2
// 4 samples per block, 256 threads.
// ---------------------------------------------------------------------------
__global__ void __launch_bounds__(256) conv_kernel(
    const float* __restrict__ x,
    const float* __restrict__ w1, const float* __restrict__ b1,
    const float* __restrict__ w2, const float* __restrict__ b2)
{
    __shared__ float xs[4][66];        // [s][0]=0 pad, [1..64]=x, [65]=0 pad
    __shared__ float p1s[4][1096];     // ic*34 + pos; pos 0 and 33 are zero pads
                                       // sample stride 1096 (%32==8) -> conflict-free
    __shared__ float w1s[96];
    __shared__ float b1s[32];
    __shared__ float w2s[64 * 97];     // oc*97 + ic*3 + t  (97%32==1 -> conflict-free)
    __shared__ float b2s[64];

    const int tid = threadIdx.x;
    const int s0  = blockIdx.x * 4;

    // ---- stage weights ----
    for (int i = tid; i < 96; i += 256) w1s[i] = w1[i];
    if (tid < 32) b1s[tid] = b1[tid];
    if (tid < 64) b2s[tid] = b2[tid];
    for (int i = tid; i < 64 * 96; i += 256) {
        int oc = i / 96, r = i % 96;
        w2s[oc * 97 + r] = w2[i];
    }
    // ---- stage input ----
    {
        int s = tid >> 6, i = tid & 63;
        xs[s][1 + i] = x[(size_t)(s0 + s) * 64 + i];
    }
    if (tid < 4)      xs[tid][0]      = 0.f;
    else if (tid < 8) xs[tid - 4][65] = 0.f;
    __syncthreads();

    // ---- phase 1: conv1 + relu + pool ----
    {
        int s    = tid >> 6;          // sample 0..3
        int c    = (tid >> 1) & 31;   // channel 0..31
        int half = tid & 1;           // which 16 pooled positions
        float ww0 = w1s[c * 3 + 0], ww1 = w1s[c * 3 + 1], ww2 = w1s[c * 3 + 2];
        float bb  = b1s[c];
        float* pr = &p1s[s][c * 34];
        if (half == 0) pr[0] = 0.f; else pr[33] = 0.f;
        const int jb = half * 16;
        #pragma unroll
        for (int j = 0; j < 16; j++) {
            int i0 = 2 * (jb + j);    // window xs[s][i0 .. i0+3]
            float a = xs[s][i0], b = xs[s][i0 + 1], cc = xs[s][i0 + 2], d = xs[s][i0 + 3];
            float o0 = bb + ww0 * a + ww1 * b  + ww2 * cc;
            float o1 = bb + ww0 * b + ww1 * cc + ww2 * d;
            pr[1 + jb + j] = fmaxf(fmaxf(o0, o1), 0.f);
        }
    }
    __syncthreads();

    // ---- phase 2: conv2 + relu + pool ----
    {
        const int oc = tid & 63;      // warp-constant sample -> p1 reads are broadcast
        const int s  = tid >> 6;
        float acc[32];
        #pragma unroll
        for (int p = 0; p < 32; p++) acc[p] = 0.f;

        const float* wrow  = &w2s[oc * 97];
        const float* pbase = &p1s[s][0];
        #pragma unroll 4
        for (int ic = 0; ic < 32; ic++) {
            float u0 = wrow[ic * 3 + 0], u1 = wrow[ic * 3 + 1], u2 = wrow[ic * 3 + 2];
            const float* pr = pbase + ic * 34;
            #pragma unroll
            for (int p = 0; p < 32; p++)
                acc[p] += u0 * pr[p] + u1 * pr[p + 1] + u2 * pr[p + 2];
        }
        const float bb = b2s[oc];
        float o[16];
        #pragma unroll
        for (int j = 0; j < 16; j++)
            o[j] = fmaxf(fmaxf(acc[2 * j], acc[2 * j + 1]) + bb, 0.f);

        float4* dst = (float4*)&g_p2[(size_t)(s0 + s) * 1024 + oc * 16];
        #pragma unroll
        for (int j = 0; j < 4; j++)
            dst[j] = make_float4(o[4 * j], o[4 * j + 1], o[4 * j + 2], o[4 * j + 3]);
    }
}

// ---------------------------------------------------------------------------
// Quantum helpers: 16-amplitude statevector in registers.
// wire w <-> bit (8 >> w) of the flat index.
// ---------------------------------------------------------------------------
__device__ __forceinline__ void apply_ry(float st[16], float c, float s, const int bit) {
    #pragma unroll
    for (int i = 0; i < 16; i++) {
        if (i & bit) continue;
        float a0 = st[i], a1 = st[i | bit];
        st[i]       = c * a0 - s * a1;
        st[i | bit] = s * a0 + c * a1;
    }
}
__device__ __forceinline__ void apply_cnot(float st[16], const int cbit, const int tbit) {
    #pragma unroll
    for (int i = 0; i < 16; i++) {
        if ((i & cbit) && !(i & tbit)) {
            float t = st[i]; st[i] = st[i | tbit]; st[i | tbit] = t;
        }
    }
}

// ---------------------------------------------------------------------------
// Kernel B: FC GEMM (M=32768, K=1024, N=64) + fused pre/tanh/quantum/post/sigmoid.
// Tile 64(M) x 64(N), 256 threads, 4x4 register blocking.
// ---------------------------------------------------------------------------
__global__ void __launch_bounds__(256) fc_quantum_kernel(
    const float* __restrict__ fc_w,  const float* __restrict__ fc_b,
    const float* __restrict__ pre_w, const float* __restrict__ pre_b,
    const float* __restrict__ q_params,
    const float* __restrict__ post_w, const float* __restrict__ post_b,
    float* __restrict__ out)
{
    __shared__ float Ast[16][68];     // [k][m], row 272B (16B aligned)
    __shared__ float Bs [16][68];     // [k][n]
    __shared__ float hs [64][65];     // fc output, pad 65 -> conflict-free column reads
    __shared__ float qc[24], qs[24];  // cos/sin of fixed layer angles / 2
    __shared__ float pws[256];        // pre_w (64,4)
    __shared__ float fbs[64];

    const int tid = threadIdx.x;
    const int m0  = blockIdx.x * 64;
    const int tx  = tid & 15, ty = tid >> 4;

    if (tid < 24) { float h = 0.5f * q_params[tid]; qc[tid] = cosf(h); qs[tid] = sinf(h); }
    if (tid < 64) fbs[tid] = fc_b[tid];
    if (tid < 256) pws[tid] = pre_w[tid];

    float acc[4][4];
    #pragma unroll
    for (int i = 0; i < 4; i++)
        #pragma unroll
        for (int j = 0; j < 4; j++) acc[i][j] = 0.f;

    const int mload  = tid >> 2;        // 0..63
    const int kload4 = (tid & 3) * 4;   // 0,4,8,12
    const int kkB    = tid >> 4;        // 0..15
    const int nnB    = (tid & 15) * 4;  // 0..60

    for (int k0 = 0; k0 < 1024; k0 += 16) {
        float4 av = *(const float4*)&g_p2[(size_t)(m0 + mload) * 1024 + k0 + kload4];
        Ast[kload4 + 0][mload] = av.x;
        Ast[kload4 + 1][mload] = av.y;
        Ast[kload4 + 2][mload] = av.z;
        Ast[kload4 + 3][mload] = av.w;
        *(float4*)&Bs[kkB][nnB] = *(const float4*)&fc_w[(size_t)(k0 + kkB) * 64 + nnB];
        __syncthreads();

        #pragma unroll
        for (int kk = 0; kk < 16; kk++) {
            float4 a = *(const float4*)&Ast[kk][ty << 2];
            float4 b = *(const float4*)&Bs[kk][tx << 2];
            float av4[4] = {a.x, a.y, a.z, a.w};
            float bv4[4] = {b.x, b.y, b.z, b.w};
            #pragma unroll
            for (int i = 0; i < 4; i++)
                #pragma unroll
                for (int j = 0; j < 4; j++)
                    acc[i][j] = fmaf(av4[i], bv4[j], acc[i][j]);
        }
        __syncthreads();
    }

    // relu(h + b) into smem
    #pragma unroll
    for (int i = 0; i < 4; i++)
        #pragma unroll
        for (int j = 0; j < 4; j++)
            hs[ty * 4 + i][tx * 4 + j] = fmaxf(acc[i][j] + fbs[tx * 4 + j], 0.f);
    __syncthreads();

    // fused epilogue: one thread per sample row
    if (tid < 64) {
        float a0 = pre_b[0], a1 = pre_b[1], a2 = pre_b[2], a3 = pre_b[3];
        const float* hr = hs[tid];
        #pragma unroll
        for (int c = 0; c < 64; c++) {
            float hv = hr[c];
            a0 = fmaf(hv, pws[c * 4 + 0], a0);
            a1 = fmaf(hv, pws[c * 4 + 1], a1);
            a2 = fmaf(hv, pws[c * 4 + 2], a2);
            a3 = fmaf(hv, pws[c * 4 + 3], a3);
        }
        // theta = (pi/2)*tanh(a); RY uses half angle -> (pi/4)*tanh(a)
        const float QP = 0.78539816339744831f;  // pi/4
        float c0, s0, c1, s1, c2, s2, c3, s3;
        sincosf(QP * tanhf(a0), &s0, &c0);
        sincosf(QP * tanhf(a1), &s1, &c1);
        sincosf(QP * tanhf(a2), &s2, &c2);
        sincosf(QP * tanhf(a3), &s3, &c3);

        float st[16];
        #pragma unroll
        for (int i = 0; i < 16; i++) st[i] = 0.25f;

        apply_ry(st, c0, s0, 8);
        apply_ry(st, c1, s1, 4);
        apply_ry(st, c2, s2, 2);
        apply_ry(st, c3, s3, 1);

        #pragma unroll
        for (int k = 0; k < 6; k++) {
            apply_cnot(st, 8, 4);   // CNOT(0,1)
            apply_cnot(st, 2, 1);   // CNOT(2,3)
            apply_cnot(st, 4, 2);   // CNOT(1,2)
            apply_ry(st, qc[4 * k + 0], qs[4 * k + 0], 8);
            apply_ry(st, qc[4 * k + 1], qs[4 * k + 1], 4);
            apply_ry(st, qc[4 * k + 2], qs[4 * k + 2], 2);
            apply_ry(st, qc[4 * k + 3], qs[4 * k + 3], 1);
        }

        float z0 = 0.f, z1 = 0.f, z2 = 0.f, z3 = 0.f;
        #pragma unroll
        for (int i = 0; i < 16; i++) {
            float p = st[i] * st[i];
            z0 += (i & 8) ? -p : p;
            z1 += (i & 4) ? -p : p;
            z2 += (i & 2) ? -p : p;
            z3 += (i & 1) ? -p : p;
        }
        float r = post_b[0];
        r = fmaf(z0, post_w[0], r);
        r = fmaf(z1, post_w[1], r);
        r = fmaf(z2, post_w[2], r);
        r = fmaf(z3, post_w[3], r);
        out[m0 + tid] = 1.f / (1.f + expf(-r));
    }
}

// ---------------------------------------------------------------------------
extern "C" void kernel_launch(void* const* d_in, const int* in_sizes, int n_in,
                              void* d_out, int out_size)
{
    const float* x      = (const float*)d_in[0];
    const float* w1     = (const float*)d_in[1];
    const float* b1     = (const float*)d_in[2];
    const float* w2     = (const float*)d_in[3];
    const float* b2     = (const float*)d_in[4];
    const float* fc_w   = (const float*)d_in[5];
    const float* fc_b   = (const float*)d_in[6];
    const float* pre_w  = (const float*)d_in[7];
    const float* pre_b  = (const float*)d_in[8];
    const float* q_par  = (const float*)d_in[9];
    const float* post_w = (const float*)d_in[10];
    const float* post_b = (const float*)d_in[11];
    float* out = (float*)d_out;

    conv_kernel<<<BATCH / 4, 256>>>(x, w1, b1, w2, b2);
    fc_quantum_kernel<<<BATCH / 64, 256>>>(fc_w, fc_b, pre_w, pre_b, q_par,
                                           post_w, post_b, out);
}